// round 2
// baseline (speedup 1.0000x reference)
#include <cuda_runtime.h>
#include <math.h>

#define BB 2
#define HH 64
#define WW_ 64
#define LL 4096
#define DD 192
#define NS 16
#define KK 4
#define RR 12
#define OO 44
#define CC 64     // chunks
#define TT 64     // chunk length (CC*TT == LL)

// ---------------- scratch (device globals; no allocation allowed) ------------
__device__ float g_z[(size_t)BB*LL*DD];            // [b][l][d]   post in_proj
__device__ float g_s[(size_t)BB*LL*DD];            // [b][l][d]   post conv+silu
__device__ float g_xdt[(size_t)BB*KK*RR*LL];       // [bk][r][l]  dt_r part of x_dbl
__device__ float g_bc[(size_t)BB*KK*LL*2*NS];      // [bk][l][32] B(16),C(16) repacked
__device__ float g_delta[(size_t)BB*KK*LL*DD];     // [bk][l][d]  softplus'd delta
__device__ float g_hbuf[(size_t)BB*KK*CC*17*DD];   // [bk][c][17][d]  hloc(16) + S
__device__ float g_h0[(size_t)BB*KK*CC*NS*DD];     // [bk][c][n][d]   chunk init state
__device__ float g_y[(size_t)BB*KK*LL*DD];         // [bk][l][d]  scan-order y
__device__ float g_yn[(size_t)BB*LL*DD];           // [b][l][d]   merged + LN

// scan-index -> canonical (h*W+w) index for direction k
__device__ __forceinline__ int lmap(int k, int l){
  switch(k){
    case 0: return l;
    case 1: return LL-1-l;
    case 2: return (l % HH)*WW_ + (l / HH);
    default: { int lr = LL-1-l; return (lr % HH)*WW_ + (lr / HH); }
  }
}

// ---------------- tiled fp32 GEMM  C[m][n] = sum_k A[m][k]*Bt[n][k] ----------
// M=8192, N=192, K=192 fixed. grid (N/64, M/64), block 256.
__device__ __forceinline__ void gemm_body(const float* __restrict__ A,
                                          const float* __restrict__ Bt,
                                          float* __restrict__ Cc){
  __shared__ float As[16][68];
  __shared__ float Bs[16][68];
  const int bm = blockIdx.y*64, bn = blockIdx.x*64;
  const int tid = threadIdx.x;
  const int tx = tid & 15, ty = tid >> 4;
  float acc[4][4];
  #pragma unroll
  for (int i=0;i<4;i++)
    #pragma unroll
    for (int j=0;j<4;j++) acc[i][j]=0.f;

  for (int k0=0;k0<192;k0+=16){
    #pragma unroll
    for (int i=0;i<4;i++){
      int idx = tid + i*256;
      int r = idx >> 4, c = idx & 15;
      As[c][r] = A [(size_t)(bm+r)*192 + k0 + c];
      Bs[c][r] = Bt[(size_t)(bn+r)*192 + k0 + c];
    }
    __syncthreads();
    #pragma unroll
    for (int kk=0;kk<16;kk++){
      float4 a = *reinterpret_cast<const float4*>(&As[kk][ty*4]);
      float4 b = *reinterpret_cast<const float4*>(&Bs[kk][tx*4]);
      acc[0][0]+=a.x*b.x; acc[0][1]+=a.x*b.y; acc[0][2]+=a.x*b.z; acc[0][3]+=a.x*b.w;
      acc[1][0]+=a.y*b.x; acc[1][1]+=a.y*b.y; acc[1][2]+=a.y*b.z; acc[1][3]+=a.y*b.w;
      acc[2][0]+=a.z*b.x; acc[2][1]+=a.z*b.y; acc[2][2]+=a.z*b.z; acc[2][3]+=a.z*b.w;
      acc[3][0]+=a.w*b.x; acc[3][1]+=a.w*b.y; acc[3][2]+=a.w*b.z; acc[3][3]+=a.w*b.w;
    }
    __syncthreads();
  }
  #pragma unroll
  for (int i=0;i<4;i++){
    float4 v = make_float4(acc[i][0],acc[i][1],acc[i][2],acc[i][3]);
    *reinterpret_cast<float4*>(&Cc[(size_t)(bm+ty*4+i)*192 + bn + tx*4]) = v;
  }
}

__global__ __launch_bounds__(256) void k_gemm_in(const float* __restrict__ A,
                                                 const float* __restrict__ Bt){
  gemm_body(A, Bt, g_z);
}
__global__ __launch_bounds__(256) void k_gemm_out(const float* __restrict__ Bt,
                                                  float* __restrict__ Cc){
  gemm_body(g_yn, Bt, Cc);
}

// ---------------- depthwise 3x3 conv + bias + SiLU ---------------------------
__global__ __launch_bounds__(256) void conv_silu(const float* __restrict__ cw,
                                                 const float* __restrict__ cb){
  int t = blockIdx.x*256 + threadIdx.x;
  if (t >= BB*LL*DD) return;
  int d = t % DD; int l = (t/DD) % LL; int b = t/(DD*LL);
  int h = l / WW_, w = l % WW_;
  float acc = cb[d];
  #pragma unroll
  for (int ky=0; ky<3; ky++){
    int hh = h + ky - 1;
    if (hh < 0 || hh >= HH) continue;
    #pragma unroll
    for (int kx=0; kx<3; kx++){
      int ww = w + kx - 1;
      if (ww < 0 || ww >= WW_) continue;
      acc += g_z[((size_t)b*LL + hh*WW_ + ww)*DD + d] * cw[d*9 + ky*3 + kx];
    }
  }
  float sg = 1.f/(1.f + __expf(-acc));
  g_s[t] = acc*sg;
}

// ---------------- x_dbl GEMM: per (b,k): C[o][l] = Wx_k[o][:] . s[map(l)][:] -
// grid (L/64, 1, B*K), block 256. Epilogue splits into g_xdt (o<12) and g_bc.
__global__ __launch_bounds__(256) void k_xdbl(const float* __restrict__ xw){
  __shared__ float As[16][68];
  __shared__ float Bs[16][68];
  const int bz = blockIdx.z; const int k = bz & 3; const int b = bz >> 2;
  const int bn = blockIdx.x*64;
  const float* A = xw + (size_t)k*OO*192;
  const int tid = threadIdx.x;
  const int tx = tid & 15, ty = tid >> 4;
  float acc[4][4];
  #pragma unroll
  for (int i=0;i<4;i++)
    #pragma unroll
    for (int j=0;j<4;j++) acc[i][j]=0.f;

  for (int k0=0;k0<192;k0+=16){
    #pragma unroll
    for (int i=0;i<4;i++){
      int idx = tid + i*256;
      int r = idx >> 4, c = idx & 15;
      As[c][r] = (r < OO) ? A[(size_t)r*192 + k0 + c] : 0.f;
      int l = bn + r;
      int lm = lmap(k, l);
      Bs[c][r] = g_s[((size_t)b*LL + lm)*DD + k0 + c];
    }
    __syncthreads();
    #pragma unroll
    for (int kk=0;kk<16;kk++){
      float4 a = *reinterpret_cast<const float4*>(&As[kk][ty*4]);
      float4 b4 = *reinterpret_cast<const float4*>(&Bs[kk][tx*4]);
      acc[0][0]+=a.x*b4.x; acc[0][1]+=a.x*b4.y; acc[0][2]+=a.x*b4.z; acc[0][3]+=a.x*b4.w;
      acc[1][0]+=a.y*b4.x; acc[1][1]+=a.y*b4.y; acc[1][2]+=a.y*b4.z; acc[1][3]+=a.y*b4.w;
      acc[2][0]+=a.z*b4.x; acc[2][1]+=a.z*b4.y; acc[2][2]+=a.z*b4.z; acc[2][3]+=a.z*b4.w;
      acc[3][0]+=a.w*b4.x; acc[3][1]+=a.w*b4.y; acc[3][2]+=a.w*b4.z; acc[3][3]+=a.w*b4.w;
    }
    __syncthreads();
  }
  #pragma unroll
  for (int i=0;i<4;i++){
    int o = ty*4 + i;
    if (o >= OO) continue;
    #pragma unroll
    for (int j=0;j<4;j++){
      int l = bn + tx*4 + j;
      float v = acc[i][j];
      if (o < RR) g_xdt[((size_t)bz*RR + o)*LL + l] = v;
      else        g_bc[((size_t)bz*LL + l)*32 + (o - RR)] = v;
    }
  }
}

// ---------------- delta projection + softplus -> g_delta[bk][l][d] -----------
// grid (D/64, L/64, B*K), block 256, K-dim = 12
__global__ __launch_bounds__(256) void k_dtproj(const float* __restrict__ dtw,
                                                const float* __restrict__ dtb){
  __shared__ float As[12][68];  // [r][l]
  __shared__ float Bs[12][68];  // [r][d]
  const int bz = blockIdx.z; const int k = bz & 3;
  const int bl0 = blockIdx.y*64;
  const int bd0 = blockIdx.x*64;
  const int tid = threadIdx.x;
  const int tx = tid & 15, ty = tid >> 4;

  for (int i=0;i<3;i++){
    int idx = tid + i*256;         // < 768 = 12*64
    int rr = idx & 63, r = idx >> 6;
    As[r][rr] = g_xdt[((size_t)bz*RR + r)*LL + bl0 + rr];
    Bs[r][rr] = dtw[(size_t)(k*DD + bd0 + rr)*RR + r];
  }
  __syncthreads();

  float acc[4][4];
  #pragma unroll
  for (int i=0;i<4;i++)
    #pragma unroll
    for (int j=0;j<4;j++) acc[i][j]=0.f;
  #pragma unroll
  for (int r=0;r<12;r++){
    float4 a = *reinterpret_cast<const float4*>(&As[r][ty*4]);
    float4 b = *reinterpret_cast<const float4*>(&Bs[r][tx*4]);
    acc[0][0]+=a.x*b.x; acc[0][1]+=a.x*b.y; acc[0][2]+=a.x*b.z; acc[0][3]+=a.x*b.w;
    acc[1][0]+=a.y*b.x; acc[1][1]+=a.y*b.y; acc[1][2]+=a.y*b.z; acc[1][3]+=a.y*b.w;
    acc[2][0]+=a.z*b.x; acc[2][1]+=a.z*b.y; acc[2][2]+=a.z*b.z; acc[2][3]+=a.z*b.w;
    acc[3][0]+=a.w*b.x; acc[3][1]+=a.w*b.y; acc[3][2]+=a.w*b.z; acc[3][3]+=a.w*b.w;
  }
  float bias[4];
  #pragma unroll
  for (int j=0;j<4;j++) bias[j] = dtb[k*DD + bd0 + tx*4 + j];
  #pragma unroll
  for (int i=0;i<4;i++){
    int l = bl0 + ty*4 + i;
    float4 v;
    float* vp = &v.x;
    #pragma unroll
    for (int j=0;j<4;j++){
      float x = acc[i][j] + bias[j];
      vp[j] = fmaxf(x, 0.f) + log1pf(__expf(-fabsf(x)));  // stable softplus
    }
    *reinterpret_cast<float4*>(&g_delta[((size_t)bz*LL + l)*DD + bd0 + tx*4]) = v;
  }
}

// ---------------- scan pass 1: chunk-local states + Sum(dt) ------------------
// thread layout: t -> d (fast), c, bk.  98304 threads.
__global__ __launch_bounds__(256) void scan1(const float* __restrict__ Alog){
  int t = blockIdx.x*256 + threadIdx.x;
  int d = t % DD;
  int rest = t / DD;
  int c = rest % CC;
  int bk = rest / CC;
  int k = bk & 3; int b = bk >> 2;

  float a[NS]; bool fast = true;
  #pragma unroll
  for (int n=0;n<NS;n++){
    a[n] = __expf(Alog[(size_t)(k*DD + d)*NS + n]);
    fast = fast && (fabsf(a[n] - (float)(n+1)) < 1e-3f);
  }
  float h[NS];
  #pragma unroll
  for (int n=0;n<NS;n++) h[n]=0.f;
  float S = 0.f;
  const int l0 = c*TT;
  const float* dp = g_delta + ((size_t)bk*LL + l0)*DD + d;

  for (int tt=0; tt<TT; tt++){
    int l = l0 + tt;
    float dt = __ldg(dp); dp += DD;
    S += dt;
    int lm = lmap(k, l);
    float u = __ldg(&g_s[((size_t)b*LL + lm)*DD + d]);
    float du = dt*u;
    const float4* bc = reinterpret_cast<const float4*>(g_bc + ((size_t)bk*LL + l)*32);
    if (fast){
      float w = __expf(-dt);
      float wp = w;
      #pragma unroll
      for (int g=0; g<4; g++){
        float4 B4 = __ldg(bc + g);
        h[4*g+0] = wp*h[4*g+0] + du*B4.x; wp *= w;
        h[4*g+1] = wp*h[4*g+1] + du*B4.y; wp *= w;
        h[4*g+2] = wp*h[4*g+2] + du*B4.z; wp *= w;
        h[4*g+3] = wp*h[4*g+3] + du*B4.w; wp *= w;
      }
    } else {
      #pragma unroll
      for (int g=0; g<4; g++){
        float4 B4 = __ldg(bc + g);
        h[4*g+0] = __expf(-dt*a[4*g+0])*h[4*g+0] + du*B4.x;
        h[4*g+1] = __expf(-dt*a[4*g+1])*h[4*g+1] + du*B4.y;
        h[4*g+2] = __expf(-dt*a[4*g+2])*h[4*g+2] + du*B4.z;
        h[4*g+3] = __expf(-dt*a[4*g+3])*h[4*g+3] + du*B4.w;
      }
    }
  }
  size_t hb = ((size_t)bk*CC + c)*17*DD + d;
  #pragma unroll
  for (int n=0;n<NS;n++) g_hbuf[hb + (size_t)n*DD] = h[n];
  g_hbuf[hb + (size_t)16*DD] = S;
}

// ---------------- scan pass 2: sequential chunk carry ------------------------
// thread per (bk, n, d): 24576 threads.
__global__ __launch_bounds__(256) void scan2(const float* __restrict__ Alog){
  int t = blockIdx.x*256 + threadIdx.x;
  int d = t % DD;
  int n = (t / DD) % NS;
  int bk = t / (DD*NS);
  int k = bk & 3;
  float An = -__expf(Alog[(size_t)(k*DD + d)*NS + n]);
  float carry = 0.f;
  for (int c=0; c<CC; c++){
    size_t hb = ((size_t)bk*CC + c)*17*DD + d;
    float hl = g_hbuf[hb + (size_t)n*DD];
    float S  = g_hbuf[hb + (size_t)16*DD];
    g_h0[(((size_t)bk*CC + c)*NS + n)*DD + d] = carry;
    carry = __expf(An*S)*carry + hl;
  }
}

// ---------------- scan pass 3: replay with correct h0, emit y ----------------
__global__ __launch_bounds__(256) void scan3(const float* __restrict__ Alog,
                                             const float* __restrict__ Dsv){
  int t = blockIdx.x*256 + threadIdx.x;
  int d = t % DD;
  int rest = t / DD;
  int c = rest % CC;
  int bk = rest / CC;
  int k = bk & 3; int b = bk >> 2;

  float a[NS]; bool fast = true;
  #pragma unroll
  for (int n=0;n<NS;n++){
    a[n] = __expf(Alog[(size_t)(k*DD + d)*NS + n]);
    fast = fast && (fabsf(a[n] - (float)(n+1)) < 1e-3f);
  }
  float h[NS];
  #pragma unroll
  for (int n=0;n<NS;n++) h[n] = g_h0[(((size_t)bk*CC + c)*NS + n)*DD + d];
  float dsv = Dsv[k*DD + d];

  const int l0 = c*TT;
  const float* dp = g_delta + ((size_t)bk*LL + l0)*DD + d;

  for (int tt=0; tt<TT; tt++){
    int l = l0 + tt;
    float dt = __ldg(dp); dp += DD;
    int lm = lmap(k, l);
    float u = __ldg(&g_s[((size_t)b*LL + lm)*DD + d]);
    float du = dt*u;
    const float4* bc = reinterpret_cast<const float4*>(g_bc + ((size_t)bk*LL + l)*32);
    float acc = dsv*u;
    if (fast){
      float w = __expf(-dt);
      float wp = w;
      #pragma unroll
      for (int g=0; g<4; g++){
        float4 B4 = __ldg(bc + g);
        float4 C4 = __ldg(bc + 4 + g);
        h[4*g+0] = wp*h[4*g+0] + du*B4.x; wp *= w; acc += h[4*g+0]*C4.x;
        h[4*g+1] = wp*h[4*g+1] + du*B4.y; wp *= w; acc += h[4*g+1]*C4.y;
        h[4*g+2] = wp*h[4*g+2] + du*B4.z; wp *= w; acc += h[4*g+2]*C4.z;
        h[4*g+3] = wp*h[4*g+3] + du*B4.w; wp *= w; acc += h[4*g+3]*C4.w;
      }
    } else {
      #pragma unroll
      for (int g=0; g<4; g++){
        float4 B4 = __ldg(bc + g);
        float4 C4 = __ldg(bc + 4 + g);
        h[4*g+0] = __expf(-dt*a[4*g+0])*h[4*g+0] + du*B4.x; acc += h[4*g+0]*C4.x;
        h[4*g+1] = __expf(-dt*a[4*g+1])*h[4*g+1] + du*B4.y; acc += h[4*g+1]*C4.y;
        h[4*g+2] = __expf(-dt*a[4*g+2])*h[4*g+2] + du*B4.z; acc += h[4*g+2]*C4.z;
        h[4*g+3] = __expf(-dt*a[4*g+3])*h[4*g+3] + du*B4.w; acc += h[4*g+3]*C4.w;
      }
    }
    g_y[((size_t)bk*LL + l)*DD + d] = acc;
  }
}

// ---------------- merge 4 directions + LayerNorm -----------------------------
// grid B*L blocks, 192 threads
__global__ __launch_bounds__(192) void merge_ln(const float* __restrict__ lng,
                                                const float* __restrict__ lnb){
  int bid = blockIdx.x;
  int lc = bid % LL; int b = bid / LL;
  int d = threadIdx.x;
  int hh = lc / WW_, ww = lc % WW_;
  int l2 = ww*HH + hh;
  size_t base = (size_t)b*KK*LL*DD;
  float v = g_y[base + ((size_t)0*LL + lc)*DD + d]
          + g_y[base + ((size_t)1*LL + (LL-1-lc))*DD + d]
          + g_y[base + ((size_t)2*LL + l2)*DD + d]
          + g_y[base + ((size_t)3*LL + (LL-1-l2))*DD + d];

  __shared__ float red[16];
  __shared__ float stats[2];
  float s1 = v, s2 = v*v;
  #pragma unroll
  for (int o=16;o>0;o>>=1){
    s1 += __shfl_down_sync(0xffffffffu, s1, o);
    s2 += __shfl_down_sync(0xffffffffu, s2, o);
  }
  int wid = d >> 5, lane = d & 31;
  if (lane == 0){ red[wid] = s1; red[8+wid] = s2; }
  __syncthreads();
  if (d == 0){
    float sa=0.f, sb=0.f;
    #pragma unroll
    for (int i=0;i<6;i++){ sa += red[i]; sb += red[8+i]; }
    float mu = sa * (1.f/DD);
    float var = sb * (1.f/DD) - mu*mu;
    stats[0] = mu;
    stats[1] = rsqrtf(var + 1e-5f);
  }
  __syncthreads();
  float mu = stats[0], rs = stats[1];
  g_yn[((size_t)b*LL + lc)*DD + d] = (v - mu)*rs*lng[d] + lnb[d];
}

// ---------------- launch ------------------------------------------------------
extern "C" void kernel_launch(void* const* d_in, const int* in_sizes, int n_in,
                              void* d_out, int out_size) {
  const float* x    = (const float*)d_in[0];
  const float* Wi   = (const float*)d_in[1];
  const float* cw   = (const float*)d_in[2];
  const float* cb   = (const float*)d_in[3];
  const float* xw   = (const float*)d_in[4];
  const float* dtw  = (const float*)d_in[5];
  const float* dtb  = (const float*)d_in[6];
  const float* Alog = (const float*)d_in[7];
  const float* Dsv  = (const float*)d_in[8];
  const float* lng  = (const float*)d_in[9];
  const float* lnb  = (const float*)d_in[10];
  const float* Wo   = (const float*)d_in[11];
  float* out = (float*)d_out;

  k_gemm_in<<<dim3(3,128), 256>>>(x, Wi);
  conv_silu<<<(BB*LL*DD + 255)/256, 256>>>(cw, cb);
  k_xdbl<<<dim3(LL/64, 1, BB*KK), 256>>>(xw);
  k_dtproj<<<dim3(DD/64, LL/64, BB*KK), 256>>>(dtw, dtb);
  scan1<<<(BB*KK*CC*DD)/256, 256>>>(Alog);
  scan2<<<(BB*KK*NS*DD)/256, 256>>>(Alog);
  scan3<<<(BB*KK*CC*DD)/256, 256>>>(Alog, Dsv);
  merge_ln<<<BB*LL, 192>>>(lng, lnb);
  k_gemm_out<<<dim3(3,128), 256>>>(Wo, out);
}

// round 3
// speedup vs baseline: 1.3264x; 1.3264x over previous
#include <cuda_runtime.h>
#include <math.h>

#define BB 2
#define HH 64
#define WW_ 64
#define LL 4096
#define DD 192
#define NS 16
#define KK 4
#define RR 12
#define OO 44
#define CC 64     // chunks
#define TT 64     // chunk length (CC*TT == LL)

// ---------------- scratch (device globals; no allocation allowed) ------------
__device__ float g_z[(size_t)BB*LL*DD];            // [b][l][d]   post in_proj
__device__ float g_s[(size_t)BB*LL*DD];            // [b][l][d]   post conv+silu (row-major spatial)
__device__ float g_st[(size_t)BB*LL*DD];           // [b][lt][d]  transposed spatial (lt = w*H+h)
__device__ float g_bc[(size_t)BB*KK*LL*2*NS];      // [bk][l][32] B(16),C(16)
__device__ float g_delta[(size_t)BB*KK*LL*DD];     // [bk][l][d]  softplus'd delta
__device__ float g_hbuf[(size_t)BB*KK*CC*17*DD];   // [bk][c][17][d]  hloc(16) + S
__device__ float g_h0[(size_t)BB*KK*CC*NS*DD];     // [bk][c][n][d]   chunk init state
__device__ float g_y[(size_t)BB*KK*LL*DD];         // [bk][l][d]  scan-order y
__device__ float g_yn[(size_t)BB*LL*DD];           // [b][l][d]   merged + LN

// ---------------- tiled fp32 GEMM  C[m][n] = sum_k A[m][k]*Bt[n][k] ----------
// M=8192, N=192, K=192. grid (3,128), block 256. float4 smem fills.
__device__ __forceinline__ void gemm_body(const float* __restrict__ A,
                                          const float* __restrict__ Bt,
                                          float* __restrict__ Cc){
  __shared__ float As[16][68];
  __shared__ float Bs[16][68];
  const int bm = blockIdx.y*64, bn = blockIdx.x*64;
  const int tid = threadIdx.x;
  const int tx = tid & 15, ty = tid >> 4;
  const int fr = tid >> 2, fq = tid & 3;      // float4 fill: row 0..63, quad 0..3
  float acc[4][4];
  #pragma unroll
  for (int i=0;i<4;i++)
    #pragma unroll
    for (int j=0;j<4;j++) acc[i][j]=0.f;

  for (int k0=0;k0<192;k0+=16){
    float4 av = *reinterpret_cast<const float4*>(&A [(size_t)(bm+fr)*192 + k0 + fq*4]);
    float4 bv = *reinterpret_cast<const float4*>(&Bt[(size_t)(bn+fr)*192 + k0 + fq*4]);
    As[fq*4+0][fr]=av.x; As[fq*4+1][fr]=av.y; As[fq*4+2][fr]=av.z; As[fq*4+3][fr]=av.w;
    Bs[fq*4+0][fr]=bv.x; Bs[fq*4+1][fr]=bv.y; Bs[fq*4+2][fr]=bv.z; Bs[fq*4+3][fr]=bv.w;
    __syncthreads();
    #pragma unroll
    for (int kk=0;kk<16;kk++){
      float4 a = *reinterpret_cast<const float4*>(&As[kk][ty*4]);
      float4 b = *reinterpret_cast<const float4*>(&Bs[kk][tx*4]);
      acc[0][0]+=a.x*b.x; acc[0][1]+=a.x*b.y; acc[0][2]+=a.x*b.z; acc[0][3]+=a.x*b.w;
      acc[1][0]+=a.y*b.x; acc[1][1]+=a.y*b.y; acc[1][2]+=a.y*b.z; acc[1][3]+=a.y*b.w;
      acc[2][0]+=a.z*b.x; acc[2][1]+=a.z*b.y; acc[2][2]+=a.z*b.z; acc[2][3]+=a.z*b.w;
      acc[3][0]+=a.w*b.x; acc[3][1]+=a.w*b.y; acc[3][2]+=a.w*b.z; acc[3][3]+=a.w*b.w;
    }
    __syncthreads();
  }
  #pragma unroll
  for (int i=0;i<4;i++){
    float4 v = make_float4(acc[i][0],acc[i][1],acc[i][2],acc[i][3]);
    *reinterpret_cast<float4*>(&Cc[(size_t)(bm+ty*4+i)*192 + bn + tx*4]) = v;
  }
}

__global__ __launch_bounds__(256) void k_gemm_in(const float* __restrict__ A,
                                                 const float* __restrict__ Bt){
  gemm_body(A, Bt, g_z);
}
__global__ __launch_bounds__(256) void k_gemm_out(const float* __restrict__ Bt,
                                                  float* __restrict__ Cc){
  gemm_body(g_yn, Bt, Cc);
}

// ---------------- depthwise 3x3 conv + bias + SiLU; writes g_s and g_st ------
// grid (6, 8, B*HH), block 256 = 32d x 8w  (spatial reuse in L1)
__global__ __launch_bounds__(256) void conv_silu(const float* __restrict__ cw,
                                                 const float* __restrict__ cb){
  int tid = threadIdx.x;
  int d = blockIdx.x*32 + (tid & 31);
  int w = blockIdx.y*8 + (tid >> 5);
  int bh = blockIdx.z; int h = bh & (HH-1); int b = bh >> 6;
  float wt[9];
  #pragma unroll
  for (int i=0;i<9;i++) wt[i] = cw[d*9+i];
  float acc = cb[d];
  #pragma unroll
  for (int ky=0; ky<3; ky++){
    int hh = h + ky - 1;
    if (hh < 0 || hh >= HH) continue;
    #pragma unroll
    for (int kx=0; kx<3; kx++){
      int ww = w + kx - 1;
      if (ww < 0 || ww >= WW_) continue;
      acc += __ldg(&g_z[((size_t)b*LL + hh*WW_ + ww)*DD + d]) * wt[ky*3+kx];
    }
  }
  float sg = 1.f/(1.f + __expf(-acc));
  float v = acc*sg;
  g_s [((size_t)b*LL + h*WW_ + w)*DD + d] = v;
  g_st[((size_t)b*LL + w*HH  + h)*DD + d] = v;
}

// ---------------- x_dbl GEMM + fused dt-proj + softplus ----------------------
// per (b,k): x_dbl[o][l] = Wx_k[o][:] . s_dir[l][:]; o<12 -> delta via rank-12
// projection (fused), o>=12 -> g_bc.  grid (64, 1, 8), block 256.
__global__ __launch_bounds__(256) void k_xdbl(const float* __restrict__ xw,
                                              const float* __restrict__ dtw,
                                              const float* __restrict__ dtb){
  __shared__ float As[16][68];
  __shared__ float Bs[16][68];
  __shared__ float sdt[12][68];     // dt_r tile [r][l-local]
  __shared__ float sw[DD][13];      // dtw[d][r], padded
  __shared__ float sb[DD];
  const int bz = blockIdx.z; const int k = bz & 3; const int b = bz >> 2;
  const int bn = blockIdx.x*64;
  const float* A = xw + (size_t)k*OO*192;
  const float* src = ((k < 2) ? g_s : g_st) + (size_t)b*LL*DD;
  const bool rev = (k & 1);
  const int tid = threadIdx.x;
  const int tx = tid & 15, ty = tid >> 4;
  const int fr = tid >> 2, fq = tid & 3;

  for (int i = tid; i < DD*RR; i += 256) sw[i/RR][i%RR] = dtw[(size_t)k*DD*RR + i];
  for (int i = tid; i < DD; i += 256)    sb[i] = dtb[k*DD + i];

  float acc[4][4];
  #pragma unroll
  for (int i=0;i<4;i++)
    #pragma unroll
    for (int j=0;j<4;j++) acc[i][j]=0.f;

  for (int k0=0;k0<192;k0+=16){
    float4 av = make_float4(0.f,0.f,0.f,0.f);
    if (fr < OO) av = *reinterpret_cast<const float4*>(&A[(size_t)fr*192 + k0 + fq*4]);
    int l = bn + fr;
    int row = rev ? (LL-1-l) : l;
    float4 bv = *reinterpret_cast<const float4*>(&src[(size_t)row*DD + k0 + fq*4]);
    As[fq*4+0][fr]=av.x; As[fq*4+1][fr]=av.y; As[fq*4+2][fr]=av.z; As[fq*4+3][fr]=av.w;
    Bs[fq*4+0][fr]=bv.x; Bs[fq*4+1][fr]=bv.y; Bs[fq*4+2][fr]=bv.z; Bs[fq*4+3][fr]=bv.w;
    __syncthreads();
    #pragma unroll
    for (int kk=0;kk<16;kk++){
      float4 a = *reinterpret_cast<const float4*>(&As[kk][ty*4]);
      float4 b4 = *reinterpret_cast<const float4*>(&Bs[kk][tx*4]);
      acc[0][0]+=a.x*b4.x; acc[0][1]+=a.x*b4.y; acc[0][2]+=a.x*b4.z; acc[0][3]+=a.x*b4.w;
      acc[1][0]+=a.y*b4.x; acc[1][1]+=a.y*b4.y; acc[1][2]+=a.y*b4.z; acc[1][3]+=a.y*b4.w;
      acc[2][0]+=a.z*b4.x; acc[2][1]+=a.z*b4.y; acc[2][2]+=a.z*b4.z; acc[2][3]+=a.z*b4.w;
      acc[3][0]+=a.w*b4.x; acc[3][1]+=a.w*b4.y; acc[3][2]+=a.w*b4.z; acc[3][3]+=a.w*b4.w;
    }
    __syncthreads();
  }
  #pragma unroll
  for (int i=0;i<4;i++){
    int o = ty*4 + i;
    if (o >= OO) continue;
    #pragma unroll
    for (int j=0;j<4;j++){
      int lloc = tx*4 + j;
      float v = acc[i][j];
      if (o < RR) sdt[o][lloc] = v;
      else        g_bc[((size_t)bz*LL + bn + lloc)*32 + (o - RR)] = v;
    }
  }
  __syncthreads();
  // fused delta projection + softplus: delta[l][d] = sp(sum_r sdt[r][l]*sw[d][r] + sb[d])
  for (int idx = tid; idx < DD*64; idx += 256){
    int d = idx % DD; int ll = idx / DD;
    float a = sb[d];
    #pragma unroll
    for (int r=0;r<RR;r++) a += sdt[r][ll]*sw[d][r];
    float e = __expf(-fabsf(a));
    float v = fmaxf(a, 0.f) + __logf(1.f + e);
    g_delta[((size_t)bz*LL + bn + ll)*DD + d] = v;
  }
}

// ---------------- scan pass 1: local states + Sum(dt) + y_local --------------
// t -> d (fast), c, bk.  98304 threads.
__global__ __launch_bounds__(256) void scan1f(const float* __restrict__ Alog,
                                              const float* __restrict__ Dsv){
  int t = blockIdx.x*256 + threadIdx.x;
  int d = t % DD;
  int rest = t / DD;
  int c = rest % CC;
  int bk = rest / CC;
  int k = bk & 3; int b = bk >> 2;

  float a[NS]; bool fast = true;
  #pragma unroll
  for (int n=0;n<NS;n++){
    a[n] = __expf(Alog[(size_t)(k*DD + d)*NS + n]);
    fast = fast && (fabsf(a[n] - (float)(n+1)) < 1e-3f);
  }
  float h[NS];
  #pragma unroll
  for (int n=0;n<NS;n++) h[n]=0.f;
  float S = 0.f;
  const float dsv = Dsv[k*DD + d];
  const int l0 = c*TT;
  const float* ubase = ((k < 2) ? g_s : g_st) + (size_t)b*LL*DD + d;
  const bool rev = (k & 1);
  const float* dp = g_delta + ((size_t)bk*LL + l0)*DD + d;
  const float4* bcp = reinterpret_cast<const float4*>(g_bc + ((size_t)bk*LL + l0)*32);
  float* yp = g_y + ((size_t)bk*LL + l0)*DD + d;

  if (fast){
    #pragma unroll 4
    for (int tt=0; tt<TT; tt++){
      float dt = __ldg(dp + (size_t)tt*DD);
      S += dt;
      int row = rev ? (LL-1-(l0+tt)) : (l0+tt);
      float u = __ldg(ubase + (size_t)row*DD);
      float du = dt*u;
      float acc = dsv*u;
      float w = __expf(-dt);
      float wp = w;
      #pragma unroll
      for (int g=0; g<4; g++){
        float4 B4 = __ldg(bcp + tt*8 + g);
        float4 C4 = __ldg(bcp + tt*8 + 4 + g);
        h[4*g+0] = wp*h[4*g+0] + du*B4.x; wp *= w; acc += h[4*g+0]*C4.x;
        h[4*g+1] = wp*h[4*g+1] + du*B4.y; wp *= w; acc += h[4*g+1]*C4.y;
        h[4*g+2] = wp*h[4*g+2] + du*B4.z; wp *= w; acc += h[4*g+2]*C4.z;
        h[4*g+3] = wp*h[4*g+3] + du*B4.w; wp *= w; acc += h[4*g+3]*C4.w;
      }
      yp[(size_t)tt*DD] = acc;
    }
  } else {
    for (int tt=0; tt<TT; tt++){
      float dt = __ldg(dp + (size_t)tt*DD);
      S += dt;
      int row = rev ? (LL-1-(l0+tt)) : (l0+tt);
      float u = __ldg(ubase + (size_t)row*DD);
      float du = dt*u;
      float acc = dsv*u;
      #pragma unroll
      for (int g=0; g<4; g++){
        float4 B4 = __ldg(bcp + tt*8 + g);
        float4 C4 = __ldg(bcp + tt*8 + 4 + g);
        h[4*g+0] = __expf(-dt*a[4*g+0])*h[4*g+0] + du*B4.x; acc += h[4*g+0]*C4.x;
        h[4*g+1] = __expf(-dt*a[4*g+1])*h[4*g+1] + du*B4.y; acc += h[4*g+1]*C4.y;
        h[4*g+2] = __expf(-dt*a[4*g+2])*h[4*g+2] + du*B4.z; acc += h[4*g+2]*C4.z;
        h[4*g+3] = __expf(-dt*a[4*g+3])*h[4*g+3] + du*B4.w; acc += h[4*g+3]*C4.w;
      }
      yp[(size_t)tt*DD] = acc;
    }
  }
  size_t hb = ((size_t)bk*CC + c)*17*DD + d;
  #pragma unroll
  for (int n=0;n<NS;n++) g_hbuf[hb + (size_t)n*DD] = h[n];
  g_hbuf[hb + (size_t)16*DD] = S;
}

// ---------------- scan pass 2: sequential chunk carry (batched loads) --------
__global__ __launch_bounds__(256) void scan2b(const float* __restrict__ Alog){
  int t = blockIdx.x*256 + threadIdx.x;
  int d = t % DD;
  int n = (t / DD) % NS;
  int bk = t / (DD*NS);
  int k = bk & 3;
  float An = -__expf(Alog[(size_t)(k*DD + d)*NS + n]);
  float carry = 0.f;
  for (int c0=0; c0<CC; c0+=8){
    float hl[8], Sv[8];
    #pragma unroll
    for (int j=0;j<8;j++){
      size_t hb = ((size_t)bk*CC + c0 + j)*17*DD + d;
      hl[j] = __ldg(&g_hbuf[hb + (size_t)n*DD]);
      Sv[j] = __ldg(&g_hbuf[hb + (size_t)16*DD]);
    }
    #pragma unroll
    for (int j=0;j<8;j++){
      g_h0[(((size_t)bk*CC + c0 + j)*NS + n)*DD + d] = carry;
      carry = __expf(An*Sv[j])*carry + hl[j];
    }
  }
}

// ---------------- scan pass 3: correction  y += C . (h0 * exp(A*P)) ----------
__global__ __launch_bounds__(256) void scan3c(const float* __restrict__ Alog){
  int t = blockIdx.x*256 + threadIdx.x;
  int d = t % DD;
  int rest = t / DD;
  int c = rest % CC;
  int bk = rest / CC;
  int k = bk & 3;
  if (c == 0) return;   // h0 == 0, no correction

  float a[NS]; bool fast = true;
  #pragma unroll
  for (int n=0;n<NS;n++){
    a[n] = __expf(Alog[(size_t)(k*DD + d)*NS + n]);
    fast = fast && (fabsf(a[n] - (float)(n+1)) < 1e-3f);
  }
  float h0[NS];
  #pragma unroll
  for (int n=0;n<NS;n++) h0[n] = g_h0[(((size_t)bk*CC + c)*NS + n)*DD + d];

  const int l0 = c*TT;
  const float* dp = g_delta + ((size_t)bk*LL + l0)*DD + d;
  const float4* bcp = reinterpret_cast<const float4*>(g_bc + ((size_t)bk*LL + l0)*32);
  float* yp = g_y + ((size_t)bk*LL + l0)*DD + d;
  float P = 0.f;

  if (fast){
    #pragma unroll 4
    for (int tt=0; tt<TT; tt++){
      float dt = __ldg(dp + (size_t)tt*DD);
      P += dt;
      float v = __expf(-P);
      float vp = v;
      float corr = 0.f;
      #pragma unroll
      for (int g=0; g<4; g++){
        float4 C4 = __ldg(bcp + tt*8 + 4 + g);
        corr = fmaf(h0[4*g+0]*vp, C4.x, corr); vp *= v;
        corr = fmaf(h0[4*g+1]*vp, C4.y, corr); vp *= v;
        corr = fmaf(h0[4*g+2]*vp, C4.z, corr); vp *= v;
        corr = fmaf(h0[4*g+3]*vp, C4.w, corr); vp *= v;
      }
      yp[(size_t)tt*DD] += corr;
    }
  } else {
    for (int tt=0; tt<TT; tt++){
      float dt = __ldg(dp + (size_t)tt*DD);
      P += dt;
      float corr = 0.f;
      #pragma unroll
      for (int g=0; g<4; g++){
        float4 C4 = __ldg(bcp + tt*8 + 4 + g);
        corr = fmaf(h0[4*g+0]*__expf(-a[4*g+0]*P), C4.x, corr);
        corr = fmaf(h0[4*g+1]*__expf(-a[4*g+1]*P), C4.y, corr);
        corr = fmaf(h0[4*g+2]*__expf(-a[4*g+2]*P), C4.z, corr);
        corr = fmaf(h0[4*g+3]*__expf(-a[4*g+3]*P), C4.w, corr);
      }
      yp[(size_t)tt*DD] += corr;
    }
  }
}

// ---------------- merge 4 directions + LayerNorm -----------------------------
__global__ __launch_bounds__(192) void merge_ln(const float* __restrict__ lng,
                                                const float* __restrict__ lnb){
  int bid = blockIdx.x;
  int lc = bid % LL; int b = bid / LL;
  int d = threadIdx.x;
  int hh = lc / WW_, ww = lc % WW_;
  int l2 = ww*HH + hh;
  size_t base = (size_t)b*KK*LL*DD;
  float v = g_y[base + ((size_t)0*LL + lc)*DD + d]
          + g_y[base + ((size_t)1*LL + (LL-1-lc))*DD + d]
          + g_y[base + ((size_t)2*LL + l2)*DD + d]
          + g_y[base + ((size_t)3*LL + (LL-1-l2))*DD + d];

  __shared__ float red[16];
  __shared__ float stats[2];
  float s1 = v, s2 = v*v;
  #pragma unroll
  for (int o=16;o>0;o>>=1){
    s1 += __shfl_down_sync(0xffffffffu, s1, o);
    s2 += __shfl_down_sync(0xffffffffu, s2, o);
  }
  int wid = d >> 5, lane = d & 31;
  if (lane == 0){ red[wid] = s1; red[8+wid] = s2; }
  __syncthreads();
  if (d == 0){
    float sa=0.f, sb=0.f;
    #pragma unroll
    for (int i=0;i<6;i++){ sa += red[i]; sb += red[8+i]; }
    float mu = sa * (1.f/DD);
    float var = sb * (1.f/DD) - mu*mu;
    stats[0] = mu;
    stats[1] = rsqrtf(var + 1e-5f);
  }
  __syncthreads();
  float mu = stats[0], rs = stats[1];
  g_yn[((size_t)b*LL + lc)*DD + d] = (v - mu)*rs*lng[d] + lnb[d];
}

// ---------------- launch ------------------------------------------------------
extern "C" void kernel_launch(void* const* d_in, const int* in_sizes, int n_in,
                              void* d_out, int out_size) {
  const float* x    = (const float*)d_in[0];
  const float* Wi   = (const float*)d_in[1];
  const float* cw   = (const float*)d_in[2];
  const float* cb   = (const float*)d_in[3];
  const float* xw   = (const float*)d_in[4];
  const float* dtw  = (const float*)d_in[5];
  const float* dtb  = (const float*)d_in[6];
  const float* Alog = (const float*)d_in[7];
  const float* Dsv  = (const float*)d_in[8];
  const float* lng  = (const float*)d_in[9];
  const float* lnb  = (const float*)d_in[10];
  const float* Wo   = (const float*)d_in[11];
  float* out = (float*)d_out;

  k_gemm_in<<<dim3(3,128), 256>>>(x, Wi);
  conv_silu<<<dim3(6,8,BB*HH), 256>>>(cw, cb);
  k_xdbl<<<dim3(LL/64, 1, BB*KK), 256>>>(xw, dtw, dtb);
  scan1f<<<(BB*KK*CC*DD)/256, 256>>>(Alog, Dsv);
  scan2b<<<(BB*KK*NS*DD)/256, 256>>>(Alog);
  scan3c<<<(BB*KK*CC*DD)/256, 256>>>(Alog);
  merge_ln<<<BB*LL, 192>>>(lng, lnb);
  k_gemm_out<<<dim3(3,128), 256>>>(Wo, out);
}